// round 11
// baseline (speedup 1.0000x reference)
#include <cuda_runtime.h>
#include <cuda_bf16.h>

#define BINS        10
#define THREADS     256
#define CTAS_PER_SM 5
#define GRID        (148 * CTAS_PER_SM)   // 740
#define NWARPS      (THREADS / 32)
#define UNIT_ITERS  2
#define UNIT_F8     (32 * UNIT_ITERS)     // 64 float8 per work unit

// Global scratch (allocation-free). Invariant: zero at every kernel entry —
// zero-initialized at load, last CTA of each run resets after writing out.
__device__ float        g_binS[BINS];
__device__ float        g_binC[BINS];
__device__ unsigned int g_ticket;
__device__ unsigned int g_next;     // dynamic work-unit counter

// 256-bit global load (sm_100+).
__device__ __forceinline__ void ldg256(const float* __restrict__ p, float v[8]) {
    asm("ld.global.nc.v8.f32 {%0,%1,%2,%3,%4,%5,%6,%7}, [%8];"
        : "=f"(v[0]), "=f"(v[1]), "=f"(v[2]), "=f"(v[3]),
          "=f"(v[4]), "=f"(v[5]), "=f"(v[6]), "=f"(v[7])
        : "l"(p));
}

// Bin index matches reference bit-for-bit: g = |p-t| fp32, idx = trunc(g*10)
// clipped to 9. bce = -log(t ? p : 1-p) = -log(1-g) for t in {0,1}.
// Slot hist[idx*THREADS + tid]: 32 lanes -> 32 consecutive 8B slots,
// conflict-free regardless of idx.
__device__ __forceinline__ void ghm_accum(float p, float t, float2* hist_tid) {
    float g   = fabsf(p - t);
    int   idx = min((int)(g * 10.0f), BINS - 1);
    float bce = -__logf(1.0f - g);
    float2* slot = hist_tid + idx * THREADS;
    float2  a = *slot;
    a.x += bce;
    a.y += 1.0f;
    *slot = a;
}

__device__ __forceinline__ void ghm_accum8(const float p[8], const float t[8],
                                           float2* h) {
    #pragma unroll
    for (int k = 0; k < 8; k++) ghm_accum(p[k], t[k], h);
}

__device__ __forceinline__ unsigned warp_claim(int lane) {
    unsigned u;
    if (lane == 0) u = atomicAdd(&g_next, 1u);
    return __shfl_sync(0xFFFFFFFFu, u, 0);
}

__global__ void __launch_bounds__(THREADS, CTAS_PER_SM)
ghm_fused_kernel(const float* __restrict__ inp,
                 const float* __restrict__ tgt,
                 int n8, int n,
                 float* __restrict__ out) {
    __shared__ float2 hist[BINS * THREADS];     // 20 KB: [bin][tid]
    __shared__ float2 scratch[BINS][NWARPS];
    __shared__ bool   s_is_last;
    const int tid  = threadIdx.x;
    const int lane = tid & 31;
    const int wid  = tid >> 5;

    #pragma unroll
    for (int b = 0; b < BINS; b++)
        hist[b * THREADS + tid] = make_float2(0.0f, 0.0f);
    __syncthreads();

    float2* hist_tid = &hist[tid];
    const unsigned units = (unsigned)(n8 / UNIT_F8);

    // ---- warp-level dynamic work claiming, claim-ahead by one unit ----
    unsigned ucur = warp_claim(lane);
    if (ucur < units) {
        unsigned unext = warp_claim(lane);

        float p[8], t[8];
        size_t f = (size_t)ucur * UNIT_F8 + lane;
        ldg256(inp + f * 8, p);
        ldg256(tgt + f * 8, t);
        int slot = 1;

        for (;;) {
            long nf = -1;
            bool rolled = false;
            if (slot < UNIT_ITERS) {                 // next iter in this unit
                nf = (long)ucur * UNIT_F8 + slot * 32 + lane;
                slot++;
            } else if (unext < units) {              // roll into claimed unit
                ucur = unext;
                nf = (long)ucur * UNIT_F8 + lane;
                slot = 1;
                rolled = true;
            }
            if (nf < 0) break;

            float q[8], w[8];
            ldg256(inp + (size_t)nf * 8, q);         // loads first...
            ldg256(tgt + (size_t)nf * 8, w);
            if (rolled)                              // ...claim off load path
                unext = warp_claim(lane);

            ghm_accum8(p, t, hist_tid);              // chain drains under loads
            #pragma unroll
            for (int k = 0; k < 8; k++) { p[k] = q[k]; t[k] = w[k]; }
        }
        ghm_accum8(p, t, hist_tid);
    }

    // Tail elements beyond whole units (grid-stride; none for n = 2^25).
    for (long j = (long)units * UNIT_F8 * 8 + blockIdx.x * THREADS + tid;
         j < n; j += (long)GRID * THREADS)
        ghm_accum(inp[j], tgt[j], hist_tid);

    __syncthreads();

    // Warp-shuffle reduction of the per-thread-private histograms.
    #pragma unroll
    for (int b = 0; b < BINS; b++) {
        float2 v = hist[b * THREADS + tid];
        #pragma unroll
        for (int off = 16; off > 0; off >>= 1) {
            v.x += __shfl_down_sync(0xFFFFFFFFu, v.x, off);
            v.y += __shfl_down_sync(0xFFFFFFFFu, v.y, off);
        }
        if (lane == 0) scratch[b][wid] = v;
    }
    __syncthreads();

    if (tid < BINS) {
        float2 s = scratch[tid][0];
        #pragma unroll
        for (int w = 1; w < NWARPS; w++) {
            s.x += scratch[tid][w].x;
            s.y += scratch[tid][w].y;
        }
        atomicAdd(&g_binS[tid], s.x);
        atomicAdd(&g_binC[tid], s.y);
    }
    __threadfence();
    __syncthreads();

    // Last CTA finalizes and resets ALL global state for the next replay.
    if (tid == 0)
        s_is_last = (atomicAdd(&g_ticket, 1u) == GRID - 1);
    __syncthreads();

    if (s_is_last && tid == 0) {
        __threadfence();
        float nb = 0.0f, accv = 0.0f;
        #pragma unroll
        for (int b = 0; b < BINS; b++) {
            float c = __ldcg(&g_binC[b]);
            float s = __ldcg(&g_binS[b]);
            if (c > 0.0f) {
                nb   += 1.0f;
                accv += s / c;
            }
        }
        out[0] = accv / fmaxf(nb, 1.0f);
        #pragma unroll
        for (int b = 0; b < BINS; b++) { g_binS[b] = 0.0f; g_binC[b] = 0.0f; }
        g_ticket = 0u;
        g_next   = 0u;
    }
}

extern "C" void kernel_launch(void* const* d_in, const int* in_sizes, int n_in,
                              void* d_out, int out_size) {
    const float* inp = (const float*)d_in[0];
    const float* tgt = (const float*)d_in[1];
    float* out = (float*)d_out;
    int n  = in_sizes[0];
    int n8 = n >> 3;

    ghm_fused_kernel<<<GRID, THREADS>>>(inp, tgt, n8, n, out);
}

// round 12
// speedup vs baseline: 1.5458x; 1.5458x over previous
#include <cuda_runtime.h>
#include <cuda_bf16.h>

#define BINS        10
#define THREADS     256
#define CTAS_PER_SM 5
#define GRID        (148 * CTAS_PER_SM)   // 740
#define NWARPS      (THREADS / 32)

// Global scratch (allocation-free). Invariant: zero at every kernel entry —
// zero-initialized at load, last CTA of each run resets after writing out.
__device__ float        g_binS[BINS];
__device__ float        g_binC[BINS];
__device__ unsigned int g_ticket;

// 256-bit global load (sm_100+): one LDG.E.256 per 8 floats.
__device__ __forceinline__ void ldg256(const float* __restrict__ p, float v[8]) {
    asm("ld.global.nc.v8.f32 {%0,%1,%2,%3,%4,%5,%6,%7}, [%8];"
        : "=f"(v[0]), "=f"(v[1]), "=f"(v[2]), "=f"(v[3]),
          "=f"(v[4]), "=f"(v[5]), "=f"(v[6]), "=f"(v[7])
        : "l"(p));
}

// Bin index matches reference bit-for-bit: g = |p-t| fp32, idx = trunc(g*10)
// clipped to 9. bce = -log(t ? p : 1-p) = -log(1-g) for t in {0,1}.
// Accumulation via fire-and-forget shared-memory reductions (REDS.ADD.F32):
// no load-back, no dependent chain, warp keeps issuing. Slots are
// thread-private (S[idx*THREADS+tid]) -> lane-contiguous, conflict-free,
// deterministic (single writer per slot).
__device__ __forceinline__ void ghm_accum(float p, float t,
                                          float* S_tid, float* C_tid) {
    float g   = fabsf(p - t);
    int   idx = min((int)(g * 10.0f), BINS - 1);
    float bce = -__logf(1.0f - g);
    atomicAdd(S_tid + idx * THREADS, bce);   // result unused -> REDS
    atomicAdd(C_tid + idx * THREADS, 1.0f);
}

__device__ __forceinline__ void ghm_accum8(const float p[8], const float t[8],
                                           float* S_tid, float* C_tid) {
    #pragma unroll
    for (int k = 0; k < 8; k++) ghm_accum(p[k], t[k], S_tid, C_tid);
}

__global__ void __launch_bounds__(THREADS, CTAS_PER_SM)
ghm_fused_kernel(const float* __restrict__ inp,
                 const float* __restrict__ tgt,
                 int n8, int n,
                 float* __restrict__ out) {
    __shared__ float S[BINS * THREADS];        // 10 KB
    __shared__ float C[BINS * THREADS];        // 10 KB
    __shared__ float2 scratch[BINS][NWARPS];
    __shared__ bool   s_is_last;
    const int tid  = threadIdx.x;
    const int lane = tid & 31;
    const int wid  = tid >> 5;

    #pragma unroll
    for (int b = 0; b < BINS; b++) {
        S[b * THREADS + tid] = 0.0f;
        C[b * THREADS + tid] = 0.0f;
    }
    __syncthreads();

    float* S_tid = &S[tid];
    float* C_tid = &C[tid];
    const int stride = GRID * THREADS;

    // Software-pipelined loop over float8 blocks: next block's two LDG.256
    // issued before the current block's 16 REDS (which are themselves
    // fire-and-forget, so the warp never waits on the histogram at all).
    int i = blockIdx.x * THREADS + tid;
    if (i < n8) {
        float p[8], t[8], q[8], u[8];
        ldg256(inp + (size_t)i * 8, p);
        ldg256(tgt + (size_t)i * 8, t);
        int j = i + stride;
        for (; j < n8; j += stride) {
            ldg256(inp + (size_t)j * 8, q);
            ldg256(tgt + (size_t)j * 8, u);
            ghm_accum8(p, t, S_tid, C_tid);
            #pragma unroll
            for (int k = 0; k < 8; k++) { p[k] = q[k]; t[k] = u[k]; }
        }
        ghm_accum8(p, t, S_tid, C_tid);
    }
    // Scalar tail (n not divisible by 8).
    for (int j = n8 * 8 + blockIdx.x * THREADS + tid; j < n; j += stride)
        ghm_accum(inp[j], tgt[j], S_tid, C_tid);

    __syncthreads();   // drains pending shared reductions

    // Warp-shuffle reduction of the per-thread-private histograms.
    #pragma unroll
    for (int b = 0; b < BINS; b++) {
        float2 v = make_float2(S[b * THREADS + tid], C[b * THREADS + tid]);
        #pragma unroll
        for (int off = 16; off > 0; off >>= 1) {
            v.x += __shfl_down_sync(0xFFFFFFFFu, v.x, off);
            v.y += __shfl_down_sync(0xFFFFFFFFu, v.y, off);
        }
        if (lane == 0) scratch[b][wid] = v;
    }
    __syncthreads();

    // Fold warp partials and push per-CTA totals into global bins.
    if (tid < BINS) {
        float2 s = scratch[tid][0];
        #pragma unroll
        for (int w = 1; w < NWARPS; w++) {
            s.x += scratch[tid][w].x;
            s.y += scratch[tid][w].y;
        }
        atomicAdd(&g_binS[tid], s.x);
        atomicAdd(&g_binC[tid], s.y);
    }
    __threadfence();
    __syncthreads();

    // Last CTA finalizes and resets state for the next graph replay.
    if (tid == 0)
        s_is_last = (atomicAdd(&g_ticket, 1u) == GRID - 1);
    __syncthreads();

    if (s_is_last && tid == 0) {
        __threadfence();
        float nb = 0.0f, accv = 0.0f;
        #pragma unroll
        for (int b = 0; b < BINS; b++) {
            float c = __ldcg(&g_binC[b]);
            float s = __ldcg(&g_binS[b]);
            if (c > 0.0f) {
                nb   += 1.0f;
                accv += s / c;
            }
        }
        out[0] = accv / fmaxf(nb, 1.0f);
        #pragma unroll
        for (int b = 0; b < BINS; b++) { g_binS[b] = 0.0f; g_binC[b] = 0.0f; }
        g_ticket = 0u;
    }
}

extern "C" void kernel_launch(void* const* d_in, const int* in_sizes, int n_in,
                              void* d_out, int out_size) {
    const float* inp = (const float*)d_in[0];
    const float* tgt = (const float*)d_in[1];
    float* out = (float*)d_out;
    int n  = in_sizes[0];
    int n8 = n >> 3;

    ghm_fused_kernel<<<GRID, THREADS>>>(inp, tgt, n8, n, out);
}